// round 4
// baseline (speedup 1.0000x reference)
#include <cuda_runtime.h>
#include <cstdint>
#include <cstddef>

// Problem constants
#define Bb     8
#define Tt     2048
#define Mm     1024           // NIN == NMEM == NOUT == 1024
#define PROWS  (Bb * Tt)      // 16384 rows
#define CL     64             // scan chunk length
#define NC     (Tt / CL)      // 32 chunks

// ---------------------------------------------------------------------------
// Scratch (static __device__ arrays; runtime allocation is forbidden)
// t-major layout for scan tensors: idx = t*(B*M) + b*M + m  (coalesced in m)
// ---------------------------------------------------------------------------
__device__ float g_r [PROWS * Mm];   // sigmoid(x@wr^T + b)
__device__ float g_og[PROWS * Mm];   // sigmoid(x@wog^T + b)
__device__ float g_zi[PROWS * Mm];   // raw x@wi^T
__device__ float g_sg[PROWS * Mm];   // sigmoid(x@wig^T + b)
__device__ float g_y [PROWS * Mm];   // softsign(h)*og, p-major for final GEMM
__device__ float g_cA[NC * Bb * Mm]; // per-chunk prod(r)
__device__ float g_cB[NC * Bb * Mm]; // per-chunk local h end
__device__ float g_h0[NC * Bb * Mm]; // h entering each chunk

// ---------------------------------------------------------------------------
// TF32 helpers
// ---------------------------------------------------------------------------
__device__ __forceinline__ unsigned f2tf(float f) {
    unsigned u;
    asm("cvt.rna.tf32.f32 %0, %1;" : "=r"(u) : "f"(f));
    return u;
}

__device__ __forceinline__ void mma8(float* c, const unsigned* a, const unsigned* b) {
    asm volatile(
        "mma.sync.aligned.m16n8k8.row.col.f32.tf32.tf32.f32 "
        "{%0,%1,%2,%3}, {%4,%5,%6,%7}, {%8,%9}, {%0,%1,%2,%3};\n"
        : "+f"(c[0]), "+f"(c[1]), "+f"(c[2]), "+f"(c[3])
        : "r"(a[0]), "r"(a[1]), "r"(a[2]), "r"(a[3]),
          "r"(b[0]), "r"(b[1]));
}

__device__ __forceinline__ float sigmf(float x) {
    return 1.0f / (1.0f + __expf(-x));
}

// ---------------------------------------------------------------------------
// TF32 GEMM:  out[p, n] = act( sum_k A[p,k] * W[n,k] + bias[n] )
// A: [16384, 1024] row-major fp32.  W: [1024, 1024] row-major (== col-major B).
// CTA tile 128x128, KTILE=16, 8 warps (2 along p x 4 along n), warp tile 64x32.
// act: 0 = none, 1 = sigmoid.  tmajor: 1 -> store at [t][b][m], 0 -> [p][m].
// ---------------------------------------------------------------------------
#define KTILE 16
#define SSTR  20   // smem row stride in 32-bit words (16 data + 4 pad; conflict-free)

__global__ void __launch_bounds__(256) gemm_tf32(
    const float* __restrict__ A, const float* __restrict__ W,
    const float* __restrict__ bias, float* __restrict__ out,
    int act, int tmajor)
{
    __shared__ __align__(16) unsigned As[2][128 * SSTR];
    __shared__ __align__(16) unsigned Bs[2][128 * SSTR];
    __shared__ float biasS[128];

    const int tid  = threadIdx.x;
    const int lane = tid & 31;
    const int wid  = tid >> 5;
    const int wp   = wid & 1;    // warp row  (2 x 64 rows)
    const int wn   = wid >> 1;   // warp col  (4 x 32 cols)
    const int pt   = blockIdx.x; // p tile (128 rows)
    const int nt   = blockIdx.y; // n tile (128 cols)

    if (tid < 128) biasS[tid] = bias ? bias[nt * 128 + tid] : 0.0f;

    const float* Ab = A + (size_t)pt * 128 * 1024;
    const float* Wb = W + (size_t)nt * 128 * 1024;

    // staging: 512 float4 per tile, 2 per thread
    const int srow0 = tid >> 2;          // 0..63
    const int sc0   = (tid & 3) * 4;     // 0,4,8,12

    float acc[4][4][4];
    #pragma unroll
    for (int i = 0; i < 4; i++)
        #pragma unroll
        for (int j = 0; j < 4; j++)
            #pragma unroll
            for (int k = 0; k < 4; k++) acc[i][j][k] = 0.0f;

    // prologue: load k-tile 0
    {
        float4 a0 = *(const float4*)(Ab + (size_t)srow0        * 1024 + sc0);
        float4 a1 = *(const float4*)(Ab + (size_t)(srow0 + 64) * 1024 + sc0);
        float4 b0 = *(const float4*)(Wb + (size_t)srow0        * 1024 + sc0);
        float4 b1 = *(const float4*)(Wb + (size_t)(srow0 + 64) * 1024 + sc0);
        uint4 u;
        u.x = f2tf(a0.x); u.y = f2tf(a0.y); u.z = f2tf(a0.z); u.w = f2tf(a0.w);
        *(uint4*)&As[0][srow0 * SSTR + sc0] = u;
        u.x = f2tf(a1.x); u.y = f2tf(a1.y); u.z = f2tf(a1.z); u.w = f2tf(a1.w);
        *(uint4*)&As[0][(srow0 + 64) * SSTR + sc0] = u;
        u.x = f2tf(b0.x); u.y = f2tf(b0.y); u.z = f2tf(b0.z); u.w = f2tf(b0.w);
        *(uint4*)&Bs[0][srow0 * SSTR + sc0] = u;
        u.x = f2tf(b1.x); u.y = f2tf(b1.y); u.z = f2tf(b1.z); u.w = f2tf(b1.w);
        *(uint4*)&Bs[0][(srow0 + 64) * SSTR + sc0] = u;
    }
    __syncthreads();

    const int lq = lane >> 2;   // 0..7
    const int lr = lane & 3;    // 0..3

    int buf = 0;
    #pragma unroll 2
    for (int kt = 0; kt < 64; kt++) {
        float4 na0, na1, nb0, nb1;
        const bool more = (kt < 63);
        if (more) {
            const float* Ak = Ab + (kt + 1) * KTILE;
            const float* Wk = Wb + (kt + 1) * KTILE;
            na0 = *(const float4*)(Ak + (size_t)srow0        * 1024 + sc0);
            na1 = *(const float4*)(Ak + (size_t)(srow0 + 64) * 1024 + sc0);
            nb0 = *(const float4*)(Wk + (size_t)srow0        * 1024 + sc0);
            nb1 = *(const float4*)(Wk + (size_t)(srow0 + 64) * 1024 + sc0);
        }

        const unsigned* as = As[buf];
        const unsigned* bs = Bs[buf];
        #pragma unroll
        for (int ks = 0; ks < 2; ks++) {
            const int kc = ks * 8 + lr;
            unsigned af[4][4];
            unsigned bf[4][2];
            #pragma unroll
            for (int mi = 0; mi < 4; mi++) {
                const unsigned* p = as + (wp * 64 + mi * 16 + lq) * SSTR + kc;
                af[mi][0] = p[0];
                af[mi][1] = p[8 * SSTR];
                af[mi][2] = p[4];
                af[mi][3] = p[8 * SSTR + 4];
            }
            #pragma unroll
            for (int ni = 0; ni < 4; ni++) {
                const unsigned* p = bs + (wn * 32 + ni * 8 + lq) * SSTR + kc;
                bf[ni][0] = p[0];
                bf[ni][1] = p[4];
            }
            #pragma unroll
            for (int mi = 0; mi < 4; mi++)
                #pragma unroll
                for (int ni = 0; ni < 4; ni++)
                    mma8(acc[mi][ni], af[mi], bf[ni]);
        }

        if (more) {
            uint4 u;
            unsigned* asn = As[buf ^ 1];
            unsigned* bsn = Bs[buf ^ 1];
            u.x = f2tf(na0.x); u.y = f2tf(na0.y); u.z = f2tf(na0.z); u.w = f2tf(na0.w);
            *(uint4*)&asn[srow0 * SSTR + sc0] = u;
            u.x = f2tf(na1.x); u.y = f2tf(na1.y); u.z = f2tf(na1.z); u.w = f2tf(na1.w);
            *(uint4*)&asn[(srow0 + 64) * SSTR + sc0] = u;
            u.x = f2tf(nb0.x); u.y = f2tf(nb0.y); u.z = f2tf(nb0.z); u.w = f2tf(nb0.w);
            *(uint4*)&bsn[srow0 * SSTR + sc0] = u;
            u.x = f2tf(nb1.x); u.y = f2tf(nb1.y); u.z = f2tf(nb1.z); u.w = f2tf(nb1.w);
            *(uint4*)&bsn[(srow0 + 64) * SSTR + sc0] = u;
            __syncthreads();
            buf ^= 1;
        }
    }

    // epilogue
    #pragma unroll
    for (int mi = 0; mi < 4; mi++) {
        #pragma unroll
        for (int half = 0; half < 2; half++) {
            const int p = pt * 128 + wp * 64 + mi * 16 + lq + half * 8;
            size_t obase;
            if (tmajor) {
                const int bb = p >> 11;      // / 2048
                const int t  = p & 2047;
                obase = (size_t)t * (Bb * Mm) + (size_t)bb * Mm;
            } else {
                obase = (size_t)p * Mm;
            }
            #pragma unroll
            for (int ni = 0; ni < 4; ni++) {
                const int cloc = wn * 32 + ni * 8 + lr * 2;
                const int col  = nt * 128 + cloc;
                float v0 = acc[mi][ni][half * 2 + 0] + biasS[cloc];
                float v1 = acc[mi][ni][half * 2 + 1] + biasS[cloc + 1];
                if (act) { v0 = sigmf(v0); v1 = sigmf(v1); }
                *(float2*)(out + obase + col) = make_float2(v0, v1);
            }
        }
    }
}

// ---------------------------------------------------------------------------
// Chunked linear scan:  h_t = h_{t-1} * r_t + zi_t * sg_t
// ---------------------------------------------------------------------------
__global__ void __launch_bounds__(256) scan_pass1() {
    const int idx = blockIdx.x * 256 + threadIdx.x;  // NC*B*M = 262144
    const int c   = idx >> 13;                        // chunk
    const int bm  = idx & 8191;                       // b*M + m
    int base = c * CL * (Bb * Mm) + bm;
    float h = 0.0f, A = 1.0f;
    #pragma unroll 8
    for (int i = 0; i < CL; i++) {
        const float r  = g_r[base];
        const float xi = g_zi[base] * g_sg[base];
        h = h * r + xi;
        A *= r;
        base += Bb * Mm;
    }
    g_cA[idx] = A;
    g_cB[idx] = h;
}

__global__ void __launch_bounds__(256) scan_mid(const float* __restrict__ mem) {
    const int bm = blockIdx.x * 256 + threadIdx.x;   // 8192
    float h = mem[bm];
    #pragma unroll
    for (int c = 0; c < NC; c++) {
        g_h0[c * (Bb * Mm) + bm] = h;
        h = g_cB[c * (Bb * Mm) + bm] + g_cA[c * (Bb * Mm) + bm] * h;
    }
}

__global__ void __launch_bounds__(256) scan_pass2(float* __restrict__ memout) {
    const int idx = blockIdx.x * 256 + threadIdx.x;
    const int c   = idx >> 13;
    const int bm  = idx & 8191;
    const int bb  = bm >> 10;
    const int m   = bm & 1023;
    float h = g_h0[idx];
    int base = c * CL * (Bb * Mm) + bm;
    size_t ybase = (size_t)bb * Tt * Mm + (size_t)(c * CL) * Mm + m;  // p-major
    #pragma unroll 8
    for (int i = 0; i < CL; i++) {
        const float r  = g_r[base];
        const float xi = g_zi[base] * g_sg[base];
        h = h * r + xi;
        const float ss = h / (1.0f + fabsf(h));   // soft_sign
        g_y[ybase] = ss * g_og[base];
        base  += Bb * Mm;
        ybase += Mm;
    }
    if (c == NC - 1 && memout) memout[bm] = h;
}

// ---------------------------------------------------------------------------
// Launch
// ---------------------------------------------------------------------------
extern "C" void kernel_launch(void* const* d_in, const int* in_sizes, int n_in,
                              void* d_out, int out_size) {
    (void)in_sizes; (void)n_in;
    const float* x     = (const float*)d_in[0];
    const float* mem   = (const float*)d_in[1];
    const float* wr_w  = (const float*)d_in[2];
    const float* wr_b  = (const float*)d_in[3];
    const float* wi_w  = (const float*)d_in[4];
    const float* wig_w = (const float*)d_in[5];
    const float* wig_b = (const float*)d_in[6];
    const float* wog_w = (const float*)d_in[7];
    const float* wog_b = (const float*)d_in[8];
    const float* wo_w  = (const float*)d_in[9];
    float* outp = (float*)d_out;

    float *p_r, *p_og, *p_zi, *p_sg, *p_y;
    cudaGetSymbolAddress((void**)&p_r,  g_r);
    cudaGetSymbolAddress((void**)&p_og, g_og);
    cudaGetSymbolAddress((void**)&p_zi, g_zi);
    cudaGetSymbolAddress((void**)&p_sg, g_sg);
    cudaGetSymbolAddress((void**)&p_y,  g_y);

    dim3 grid(PROWS / 128, Mm / 128);   // 128 x 8
    dim3 blk(256);

    // four input projections (t-major outputs for the scan)
    gemm_tf32<<<grid, blk>>>(x, wr_w,  wr_b,    p_r,  1, 1);
    gemm_tf32<<<grid, blk>>>(x, wog_w, wog_b,   p_og, 1, 1);
    gemm_tf32<<<grid, blk>>>(x, wi_w,  nullptr, p_zi, 0, 1);
    gemm_tf32<<<grid, blk>>>(x, wig_w, wig_b,   p_sg, 1, 1);

    // chunked scan
    scan_pass1<<<(NC * Bb * Mm) / 256, 256>>>();
    scan_mid<<<(Bb * Mm) / 256, 256>>>(mem);
    float* memout = (out_size >= PROWS * Mm + Bb * Mm) ? (outp + (size_t)PROWS * Mm)
                                                       : nullptr;
    scan_pass2<<<(NC * Bb * Mm) / 256, 256>>>(memout);

    // output projection, written straight to d_out (p-major)
    gemm_tf32<<<grid, blk>>>(p_y, wo_w, nullptr, outp, 0, 0);
}

// round 7
// speedup vs baseline: 1.2542x; 1.2542x over previous
#include <cuda_runtime.h>
#include <cstdint>
#include <cstddef>

// ---------------------------------------------------------------------------
// Problem constants
// ---------------------------------------------------------------------------
#define Bb     8
#define Tt     2048
#define Mm     1024
#define PROWS  (Bb * Tt)      // 16384
#define CL     64             // scan chunk length
#define NC     (Tt / CL)      // 32 chunks

// ---------------------------------------------------------------------------
// Scratch (static __device__ arrays; runtime allocation is forbidden)
// ---------------------------------------------------------------------------
__device__ float g_r [PROWS * Mm];   // sigmoid(x@wr^T + b)   (t-major)
__device__ float g_og[PROWS * Mm];   // sigmoid(x@wog^T + b)  (t-major)
__device__ float g_zi[PROWS * Mm];   // raw x@wi^T            (t-major)
__device__ float g_sg[PROWS * Mm];   // sigmoid(x@wig^T + b)  (t-major)
__device__ float g_y [PROWS * Mm];   // softsign(h)*og, p-major, tf32-rounded
__device__ float g_xc[PROWS * Mm];   // x rounded to tf32 (rna)
__device__ float g_w0[Mm * Mm];      // wr  rounded
__device__ float g_w1[Mm * Mm];      // wog rounded
__device__ float g_w2[Mm * Mm];      // wi  rounded
__device__ float g_w3[Mm * Mm];      // wig rounded
__device__ float g_w4[Mm * Mm];      // wo  rounded
__device__ float g_cA[NC * Bb * Mm];
__device__ float g_cB[NC * Bb * Mm];
__device__ float g_h0[NC * Bb * Mm];

// ---------------------------------------------------------------------------
// Helpers
// ---------------------------------------------------------------------------
__device__ __forceinline__ unsigned f2tf(float f) {
    unsigned u;
    asm("cvt.rna.tf32.f32 %0, %1;" : "=r"(u) : "f"(f));
    return u;
}
__device__ __forceinline__ float sigmf(float x) {
    return 1.0f / (1.0f + __expf(-x));
}
__device__ __forceinline__ uint32_t smem_u32(const void* p) {
    uint32_t a;
    asm("{ .reg .u64 t; cvta.to.shared.u64 t, %1; cvt.u32.u64 %0, t; }" : "=r"(a) : "l"(p));
    return a;
}
__device__ __forceinline__ void mma8(float* c, const unsigned* a, const unsigned* b) {
    asm volatile(
        "mma.sync.aligned.m16n8k8.row.col.f32.tf32.tf32.f32 "
        "{%0,%1,%2,%3}, {%4,%5,%6,%7}, {%8,%9}, {%0,%1,%2,%3};\n"
        : "+f"(c[0]), "+f"(c[1]), "+f"(c[2]), "+f"(c[3])
        : "r"(a[0]), "r"(a[1]), "r"(a[2]), "r"(a[3]),
          "r"(b[0]), "r"(b[1]));
}
#define CP16(sp, gp) asm volatile("cp.async.cg.shared.global [%0], [%1], 16;" :: "r"(sp), "l"(gp) : "memory")

// ---------------------------------------------------------------------------
// tf32 rna conversion pre-pass (inputs already fp32; round once, GEMMs then
// stream raw bits through cp.async with no per-tile conversion work)
// ---------------------------------------------------------------------------
__global__ void __launch_bounds__(256) cvt_tf32(const float4* __restrict__ s,
                                                float4* __restrict__ d, int n4) {
    int i = blockIdx.x * 256 + threadIdx.x;
    if (i < n4) {
        float4 v = s[i];
        float4 o;
        o.x = __uint_as_float(f2tf(v.x));
        o.y = __uint_as_float(f2tf(v.y));
        o.z = __uint_as_float(f2tf(v.z));
        o.w = __uint_as_float(f2tf(v.w));
        d[i] = o;
    }
}

// ---------------------------------------------------------------------------
// TF32 GEMM (mma.sync path; tcgen05 is rejected by this toolchain's .target):
//   out[p, n] = act( sum_k A[p,k] * W[n,k] + bias[n] )
//   A [16384,1024] row-major tf32-rounded fp32 bits, W [1024,1024] row-major.
//   CTA 128x128, 4 warps (warp tile 64x64), KTILE=32, cp.async double buffer.
// ---------------------------------------------------------------------------
#define KT2   32                 // k elements per tile
#define AST   36                 // smem row stride (32 data + 4 pad words)
#define TILE_WORDS (128 * AST)   // per array per buffer
#define SMEM_SZ (2 * 2 * TILE_WORDS * 4 + 512 + 128)

__device__ __forceinline__ void load_tile2(const float* Ab, const float* Wb,
                                           int kt, uint32_t abase, uint32_t bbase,
                                           int tid) {
    const int k0  = kt * KT2;
    const int row = tid >> 3;            // 0..15 base rows (x8 chunk groups)
    const int col = tid & 7;             // 16B chunk in row
    #pragma unroll
    for (int i = 0; i < 8; i++) {        // A: 128 rows x 8 chunks
        const int r = i * 16 + row;
        CP16(abase + r * (AST * 4) + col * 16,
             Ab + (size_t)r * Mm + k0 + col * 4);
    }
    #pragma unroll
    for (int i = 0; i < 8; i++) {        // B: 128 rows x 8 chunks
        const int r = i * 16 + row;
        CP16(bbase + r * (AST * 4) + col * 16,
             Wb + (size_t)r * Mm + k0 + col * 4);
    }
    asm volatile("cp.async.commit_group;" ::: "memory");
}

__global__ void __launch_bounds__(128, 2) gemm_tf32(
    const float* __restrict__ A, const float* __restrict__ W,
    const float* __restrict__ bias, float* __restrict__ out,
    int act, int tmajor)
{
    extern __shared__ char smem[];
    unsigned* As = (unsigned*)smem;                        // [2][TILE_WORDS]
    unsigned* Bs = (unsigned*)smem + 2 * TILE_WORDS;       // [2][TILE_WORDS]
    float* biasS = (float*)((unsigned*)smem + 4 * TILE_WORDS);
    const uint32_t sA = smem_u32(As);
    const uint32_t sB = smem_u32(Bs);

    const int tid  = threadIdx.x;
    const int lane = tid & 31;
    const int wid  = tid >> 5;
    const int wp   = wid & 1;     // warp M half (2 x 64)
    const int wn   = wid >> 1;    // warp N half (2 x 64)
    const int pt   = blockIdx.x;
    const int nt   = blockIdx.y;
    const int lq   = lane >> 2;   // 0..7
    const int lr   = lane & 3;    // 0..3

    biasS[tid] = bias ? bias[nt * 128 + tid] : 0.0f;

    const float* Ab = A + (size_t)pt * 128 * Mm;
    const float* Wb = W + (size_t)nt * 128 * Mm;

    float acc[4][8][4];
    #pragma unroll
    for (int i = 0; i < 4; i++)
        #pragma unroll
        for (int j = 0; j < 8; j++)
            #pragma unroll
            for (int k = 0; k < 4; k++) acc[i][j][k] = 0.0f;

    load_tile2(Ab, Wb, 0, sA, sB, tid);

    const int NTK = Mm / KT2;     // 32
    for (int kt = 0; kt < NTK; kt++) {
        const int buf = kt & 1;
        if (kt + 1 < NTK) {
            load_tile2(Ab, Wb, kt + 1,
                       sA + (buf ^ 1) * (TILE_WORDS * 4),
                       sB + (buf ^ 1) * (TILE_WORDS * 4), tid);
            asm volatile("cp.async.wait_group 1;" ::: "memory");
        } else {
            asm volatile("cp.async.wait_group 0;" ::: "memory");
        }
        __syncthreads();

        const unsigned* as = As + buf * TILE_WORDS;
        const unsigned* bs = Bs + buf * TILE_WORDS;
        #pragma unroll
        for (int ks = 0; ks < 4; ks++) {
            const int kc = ks * 8 + lr;
            unsigned af[4][4], bf[8][2];
            #pragma unroll
            for (int mi = 0; mi < 4; mi++) {
                const unsigned* p = as + (wp * 64 + mi * 16 + lq) * AST + kc;
                af[mi][0] = p[0];
                af[mi][1] = p[8 * AST];
                af[mi][2] = p[4];
                af[mi][3] = p[8 * AST + 4];
            }
            #pragma unroll
            for (int ni = 0; ni < 8; ni++) {
                const unsigned* p = bs + (wn * 64 + ni * 8 + lq) * AST + kc;
                bf[ni][0] = p[0];
                bf[ni][1] = p[4];
            }
            #pragma unroll
            for (int mi = 0; mi < 4; mi++)
                #pragma unroll
                for (int ni = 0; ni < 8; ni++)
                    mma8(acc[mi][ni], af[mi], bf[ni]);
        }
        __syncthreads();
    }

    // epilogue: direct float2 stores (fully coalesced pairs)
    #pragma unroll
    for (int mi = 0; mi < 4; mi++) {
        #pragma unroll
        for (int half = 0; half < 2; half++) {
            const int p = pt * 128 + wp * 64 + mi * 16 + lq + half * 8;
            size_t obase;
            if (tmajor) {
                const int bb = p >> 11;
                const int t  = p & 2047;
                obase = (size_t)t * (Bb * Mm) + (size_t)bb * Mm;
            } else {
                obase = (size_t)p * Mm;
            }
            #pragma unroll
            for (int ni = 0; ni < 8; ni++) {
                const int cloc = wn * 64 + ni * 8 + lr * 2;
                const int col  = nt * 128 + cloc;
                float v0 = acc[mi][ni][half * 2 + 0] + biasS[cloc];
                float v1 = acc[mi][ni][half * 2 + 1] + biasS[cloc + 1];
                if (act) { v0 = sigmf(v0); v1 = sigmf(v1); }
                *(float2*)(out + obase + col) = make_float2(v0, v1);
            }
        }
    }
}

// ---------------------------------------------------------------------------
// Chunked linear scan:  h_t = h_{t-1} * r_t + zi_t * sg_t
// ---------------------------------------------------------------------------
__global__ void __launch_bounds__(256) scan_pass1() {
    const int idx = blockIdx.x * 256 + threadIdx.x;
    const int c   = idx >> 13;
    const int bm  = idx & 8191;
    int base = c * CL * (Bb * Mm) + bm;
    float h = 0.0f, A = 1.0f;
    #pragma unroll 8
    for (int i = 0; i < CL; i++) {
        const float r  = g_r[base];
        const float xi = g_zi[base] * g_sg[base];
        h = h * r + xi;
        A *= r;
        base += Bb * Mm;
    }
    g_cA[idx] = A;
    g_cB[idx] = h;
}

__global__ void __launch_bounds__(256) scan_mid(const float* __restrict__ mem) {
    const int bm = blockIdx.x * 256 + threadIdx.x;
    float h = mem[bm];
    #pragma unroll
    for (int c = 0; c < NC; c++) {
        g_h0[c * (Bb * Mm) + bm] = h;
        h = g_cB[c * (Bb * Mm) + bm] + g_cA[c * (Bb * Mm) + bm] * h;
    }
}

__global__ void __launch_bounds__(256) scan_pass2(float* __restrict__ memout) {
    const int idx = blockIdx.x * 256 + threadIdx.x;
    const int c   = idx >> 13;
    const int bm  = idx & 8191;
    const int bb  = bm >> 10;
    const int m   = bm & 1023;
    float h = g_h0[idx];
    int base = c * CL * (Bb * Mm) + bm;
    size_t ybase = (size_t)bb * Tt * Mm + (size_t)(c * CL) * Mm + m;
    #pragma unroll 8
    for (int i = 0; i < CL; i++) {
        const float r  = g_r[base];
        const float xi = g_zi[base] * g_sg[base];
        h = h * r + xi;
        const float ss = h / (1.0f + fabsf(h));
        // pre-round for the tf32 output GEMM (keeps its operands rna-rounded)
        g_y[ybase] = __uint_as_float(f2tf(ss * g_og[base]));
        base  += Bb * Mm;
        ybase += Mm;
    }
    if (c == NC - 1 && memout) memout[bm] = h;
}

// ---------------------------------------------------------------------------
// Launch
// ---------------------------------------------------------------------------
extern "C" void kernel_launch(void* const* d_in, const int* in_sizes, int n_in,
                              void* d_out, int out_size) {
    (void)in_sizes; (void)n_in;
    const float* x     = (const float*)d_in[0];
    const float* mem   = (const float*)d_in[1];
    const float* wr_w  = (const float*)d_in[2];
    const float* wr_b  = (const float*)d_in[3];
    const float* wi_w  = (const float*)d_in[4];
    const float* wig_w = (const float*)d_in[5];
    const float* wig_b = (const float*)d_in[6];
    const float* wog_w = (const float*)d_in[7];
    const float* wog_b = (const float*)d_in[8];
    const float* wo_w  = (const float*)d_in[9];
    float* outp = (float*)d_out;

    float *p_r, *p_og, *p_zi, *p_sg, *p_y, *p_xc;
    float *p_w0, *p_w1, *p_w2, *p_w3, *p_w4;
    cudaGetSymbolAddress((void**)&p_r,  g_r);
    cudaGetSymbolAddress((void**)&p_og, g_og);
    cudaGetSymbolAddress((void**)&p_zi, g_zi);
    cudaGetSymbolAddress((void**)&p_sg, g_sg);
    cudaGetSymbolAddress((void**)&p_y,  g_y);
    cudaGetSymbolAddress((void**)&p_xc, g_xc);
    cudaGetSymbolAddress((void**)&p_w0, g_w0);
    cudaGetSymbolAddress((void**)&p_w1, g_w1);
    cudaGetSymbolAddress((void**)&p_w2, g_w2);
    cudaGetSymbolAddress((void**)&p_w3, g_w3);
    cudaGetSymbolAddress((void**)&p_w4, g_w4);

    static bool attr_done = false;
    if (!attr_done) {
        cudaFuncSetAttribute(gemm_tf32, cudaFuncAttributeMaxDynamicSharedMemorySize, SMEM_SZ);
        attr_done = true;
    }

    // rna pre-rounding to tf32 (GEMMs then need no in-kernel conversion)
    const int nx4 = (PROWS * Mm) / 4;
    const int nw4 = (Mm * Mm) / 4;
    cvt_tf32<<<(nx4 + 255) / 256, 256>>>((const float4*)x,     (float4*)p_xc, nx4);
    cvt_tf32<<<(nw4 + 255) / 256, 256>>>((const float4*)wr_w,  (float4*)p_w0, nw4);
    cvt_tf32<<<(nw4 + 255) / 256, 256>>>((const float4*)wog_w, (float4*)p_w1, nw4);
    cvt_tf32<<<(nw4 + 255) / 256, 256>>>((const float4*)wi_w,  (float4*)p_w2, nw4);
    cvt_tf32<<<(nw4 + 255) / 256, 256>>>((const float4*)wig_w, (float4*)p_w3, nw4);
    cvt_tf32<<<(nw4 + 255) / 256, 256>>>((const float4*)wo_w,  (float4*)p_w4, nw4);

    dim3 grid(PROWS / 128, Mm / 128);   // 128 x 8
    dim3 blk(128);

    // four input projections (t-major outputs for the scan)
    gemm_tf32<<<grid, blk, SMEM_SZ>>>(p_xc, p_w0, wr_b,    p_r,  1, 1);
    gemm_tf32<<<grid, blk, SMEM_SZ>>>(p_xc, p_w1, wog_b,   p_og, 1, 1);
    gemm_tf32<<<grid, blk, SMEM_SZ>>>(p_xc, p_w2, nullptr, p_zi, 0, 1);
    gemm_tf32<<<grid, blk, SMEM_SZ>>>(p_xc, p_w3, wig_b,   p_sg, 1, 1);

    // chunked scan
    scan_pass1<<<(NC * Bb * Mm) / 256, 256>>>();
    scan_mid<<<(Bb * Mm) / 256, 256>>>(mem);
    float* memout = (out_size >= PROWS * Mm + Bb * Mm) ? (outp + (size_t)PROWS * Mm)
                                                       : nullptr;
    scan_pass2<<<(NC * Bb * Mm) / 256, 256>>>(memout);

    // output projection straight to d_out (p-major)
    gemm_tf32<<<grid, blk, SMEM_SZ>>>(p_y, p_w4, nullptr, outp, 0, 0);
}

// round 10
// speedup vs baseline: 1.2951x; 1.0326x over previous
#include <cuda_runtime.h>
#include <cstdint>
#include <cstddef>

// ---------------------------------------------------------------------------
// Problem constants
// ---------------------------------------------------------------------------
#define Bb     8
#define Tt     2048
#define Mm     1024
#define PROWS  (Bb * Tt)      // 16384
#define CL     64             // scan chunk length
#define NC     (Tt / CL)      // 32 chunks

// ---------------------------------------------------------------------------
// Scratch (static __device__ arrays; runtime allocation is forbidden)
// ---------------------------------------------------------------------------
__device__ float g_r [PROWS * Mm];   // sigmoid(x@wr^T + b)   (t-major)
__device__ float g_og[PROWS * Mm];   // sigmoid(x@wog^T + b)  (t-major)
__device__ float g_zi[PROWS * Mm];   // raw x@wi^T            (t-major)
__device__ float g_sg[PROWS * Mm];   // sigmoid(x@wig^T + b)  (t-major)
__device__ float g_y [PROWS * Mm];   // softsign(h)*og, p-major, tf32-rounded
__device__ float g_xc[PROWS * Mm];   // x rounded to tf32 (rna)
__device__ float g_w0[Mm * Mm];      // wr  rounded
__device__ float g_w1[Mm * Mm];      // wog rounded
__device__ float g_w2[Mm * Mm];      // wi  rounded
__device__ float g_w3[Mm * Mm];      // wig rounded
__device__ float g_w4[Mm * Mm];      // wo  rounded
__device__ float g_cA[NC * Bb * Mm];
__device__ float g_cB[NC * Bb * Mm];
__device__ float g_h0[NC * Bb * Mm];

// ---------------------------------------------------------------------------
// Helpers
// ---------------------------------------------------------------------------
__device__ __forceinline__ unsigned f2tf(float f) {
    unsigned u;
    asm("cvt.rna.tf32.f32 %0, %1;" : "=r"(u) : "f"(f));
    return u;
}
__device__ __forceinline__ float sigmf(float x) {
    return 1.0f / (1.0f + __expf(-x));
}
__device__ __forceinline__ uint32_t smem_u32(const void* p) {
    uint32_t a;
    asm("{ .reg .u64 t; cvta.to.shared.u64 t, %1; cvt.u32.u64 %0, t; }" : "=r"(a) : "l"(p));
    return a;
}
__device__ __forceinline__ void mma8(float* c, const unsigned* a, const unsigned* b) {
    asm volatile(
        "mma.sync.aligned.m16n8k8.row.col.f32.tf32.tf32.f32 "
        "{%0,%1,%2,%3}, {%4,%5,%6,%7}, {%8,%9}, {%0,%1,%2,%3};\n"
        : "+f"(c[0]), "+f"(c[1]), "+f"(c[2]), "+f"(c[3])
        : "r"(a[0]), "r"(a[1]), "r"(a[2]), "r"(a[3]),
          "r"(b[0]), "r"(b[1]));
}
#define CP16(sp, gp) asm volatile("cp.async.cg.shared.global [%0], [%1], 16;" :: "r"(sp), "l"(gp) : "memory")

// ---------------------------------------------------------------------------
// tf32 rna conversion pre-pass
// ---------------------------------------------------------------------------
__global__ void __launch_bounds__(256) cvt_tf32(const float4* __restrict__ s,
                                                float4* __restrict__ d, int n4) {
    int i = blockIdx.x * 256 + threadIdx.x;
    if (i < n4) {
        float4 v = s[i];
        float4 o;
        o.x = __uint_as_float(f2tf(v.x));
        o.y = __uint_as_float(f2tf(v.y));
        o.z = __uint_as_float(f2tf(v.z));
        o.w = __uint_as_float(f2tf(v.w));
        d[i] = o;
    }
}

// all 5 weight matrices in one launch: grid = (Mm*Mm/4/256, 5)
struct CvtBatch { const float4* s[5]; float4* d[5]; };
__global__ void __launch_bounds__(256) cvt_tf32_w(CvtBatch cb) {
    const int w = blockIdx.y;
    const float4* s = cb.s[w];
    float4*       d = cb.d[w];
    int i = blockIdx.x * 256 + threadIdx.x;
    float4 v = s[i];
    float4 o;
    o.x = __uint_as_float(f2tf(v.x));
    o.y = __uint_as_float(f2tf(v.y));
    o.z = __uint_as_float(f2tf(v.z));
    o.w = __uint_as_float(f2tf(v.w));
    d[i] = o;
}

// ---------------------------------------------------------------------------
// TF32 GEMM (mma.sync; tcgen05 rejected by this toolchain's .target sm_103):
//   out[p, n] = act( sum_k A[p,k] * W[n,k] + bias[n] )
//   CTA 128x128, 4 warps (warp tile 64x64), KTILE=32.
//   Double buffer, ONE __syncthreads per k-iter: next-tile cp.async is issued
//   after the barrier, at which point the previous compute (sole reader of
//   that buffer) has finished — no trailing barrier needed.
//   grid.z batches up to 4 independent (W, bias, out, act) against shared A.
// ---------------------------------------------------------------------------
#define KT2   32                 // k elements per tile
#define AST   36                 // smem row stride (32 data + 4 pad words)
#define TILE_WORDS (128 * AST)   // per array per buffer
#define SMEM_SZ (2 * 2 * TILE_WORDS * 4 + 512 + 128)

struct GemmBatch {
    const float* W[4];
    const float* bias[4];
    float*       out[4];
    int          act[4];
    int          tmajor;
};

__device__ __forceinline__ void load_tile2(const float* Ab, const float* Wb,
                                           int kt, uint32_t abase, uint32_t bbase,
                                           int tid) {
    const int k0  = kt * KT2;
    const int row = tid >> 3;            // 0..15 base rows
    const int col = tid & 7;             // 16B chunk in row
    #pragma unroll
    for (int i = 0; i < 8; i++) {        // A: 128 rows x 8 chunks
        const int r = i * 16 + row;
        CP16(abase + r * (AST * 4) + col * 16,
             Ab + (size_t)r * Mm + k0 + col * 4);
    }
    #pragma unroll
    for (int i = 0; i < 8; i++) {        // B: 128 rows x 8 chunks
        const int r = i * 16 + row;
        CP16(bbase + r * (AST * 4) + col * 16,
             Wb + (size_t)r * Mm + k0 + col * 4);
    }
    asm volatile("cp.async.commit_group;" ::: "memory");
}

__global__ void __launch_bounds__(128, 2) gemm_tf32(
    const float* __restrict__ A, GemmBatch gb)
{
    extern __shared__ char smem[];
    unsigned* As = (unsigned*)smem;                        // [2][TILE_WORDS]
    unsigned* Bs = (unsigned*)smem + 2 * TILE_WORDS;       // [2][TILE_WORDS]
    float* biasS = (float*)((unsigned*)smem + 4 * TILE_WORDS);
    const uint32_t sA = smem_u32(As);
    const uint32_t sB = smem_u32(Bs);

    const int z    = blockIdx.z;
    const float* W    = gb.W[z];
    const float* bias = gb.bias[z];
    float*       out  = gb.out[z];
    const int    act  = gb.act[z];
    const int tmajor  = gb.tmajor;

    const int tid  = threadIdx.x;
    const int lane = tid & 31;
    const int wid  = tid >> 5;
    const int wp   = wid & 1;     // warp M half (2 x 64)
    const int wn   = wid >> 1;    // warp N half (2 x 64)
    const int pt   = blockIdx.x;
    const int nt   = blockIdx.y;
    const int lq   = lane >> 2;   // 0..7
    const int lr   = lane & 3;    // 0..3

    biasS[tid] = bias ? bias[nt * 128 + tid] : 0.0f;

    const float* Ab = A + (size_t)pt * 128 * Mm;
    const float* Wb = W + (size_t)nt * 128 * Mm;

    float acc[4][8][4];
    #pragma unroll
    for (int i = 0; i < 4; i++)
        #pragma unroll
        for (int j = 0; j < 8; j++)
            #pragma unroll
            for (int k = 0; k < 4; k++) acc[i][j][k] = 0.0f;

    load_tile2(Ab, Wb, 0, sA, sB, tid);

    const int NTK = Mm / KT2;     // 32
    for (int kt = 0; kt < NTK; kt++) {
        const int buf = kt & 1;
        asm volatile("cp.async.wait_group 0;" ::: "memory");
        __syncthreads();
        if (kt + 1 < NTK)
            load_tile2(Ab, Wb, kt + 1,
                       sA + (buf ^ 1) * (TILE_WORDS * 4),
                       sB + (buf ^ 1) * (TILE_WORDS * 4), tid);

        const unsigned* as = As + buf * TILE_WORDS;
        const unsigned* bs = Bs + buf * TILE_WORDS;
        #pragma unroll
        for (int ks = 0; ks < 4; ks++) {
            const int kc = ks * 8 + lr;
            unsigned af[4][4], bf[8][2];
            #pragma unroll
            for (int mi = 0; mi < 4; mi++) {
                const unsigned* p = as + (wp * 64 + mi * 16 + lq) * AST + kc;
                af[mi][0] = p[0];
                af[mi][1] = p[8 * AST];
                af[mi][2] = p[4];
                af[mi][3] = p[8 * AST + 4];
            }
            #pragma unroll
            for (int ni = 0; ni < 8; ni++) {
                const unsigned* p = bs + (wn * 64 + ni * 8 + lq) * AST + kc;
                bf[ni][0] = p[0];
                bf[ni][1] = p[4];
            }
            #pragma unroll
            for (int mi = 0; mi < 4; mi++)
                #pragma unroll
                for (int ni = 0; ni < 8; ni++)
                    mma8(acc[mi][ni], af[mi], bf[ni]);
        }
    }

    // epilogue: direct float2 stores
    #pragma unroll
    for (int mi = 0; mi < 4; mi++) {
        #pragma unroll
        for (int half = 0; half < 2; half++) {
            const int p = pt * 128 + wp * 64 + mi * 16 + lq + half * 8;
            size_t obase;
            if (tmajor) {
                const int bb = p >> 11;
                const int t  = p & 2047;
                obase = (size_t)t * (Bb * Mm) + (size_t)bb * Mm;
            } else {
                obase = (size_t)p * Mm;
            }
            #pragma unroll
            for (int ni = 0; ni < 8; ni++) {
                const int cloc = wn * 64 + ni * 8 + lr * 2;
                const int col  = nt * 128 + cloc;
                float v0 = acc[mi][ni][half * 2 + 0] + biasS[cloc];
                float v1 = acc[mi][ni][half * 2 + 1] + biasS[cloc + 1];
                if (act) { v0 = sigmf(v0); v1 = sigmf(v1); }
                *(float2*)(out + obase + col) = make_float2(v0, v1);
            }
        }
    }
}

// ---------------------------------------------------------------------------
// Chunked linear scan:  h_t = h_{t-1} * r_t + zi_t * sg_t
// ---------------------------------------------------------------------------
__global__ void __launch_bounds__(256) scan_pass1() {
    const int idx = blockIdx.x * 256 + threadIdx.x;
    const int c   = idx >> 13;
    const int bm  = idx & 8191;
    int base = c * CL * (Bb * Mm) + bm;
    float h = 0.0f, A = 1.0f;
    #pragma unroll 8
    for (int i = 0; i < CL; i++) {
        const float r  = g_r[base];
        const float xi = g_zi[base] * g_sg[base];
        h = h * r + xi;
        A *= r;
        base += Bb * Mm;
    }
    g_cA[idx] = A;
    g_cB[idx] = h;
}

__global__ void __launch_bounds__(256) scan_mid(const float* __restrict__ mem) {
    const int bm = blockIdx.x * 256 + threadIdx.x;
    float h = mem[bm];
    #pragma unroll
    for (int c = 0; c < NC; c++) {
        g_h0[c * (Bb * Mm) + bm] = h;
        h = g_cB[c * (Bb * Mm) + bm] + g_cA[c * (Bb * Mm) + bm] * h;
    }
}

__global__ void __launch_bounds__(256) scan_pass2(float* __restrict__ memout) {
    const int idx = blockIdx.x * 256 + threadIdx.x;
    const int c   = idx >> 13;
    const int bm  = idx & 8191;
    const int bb  = bm >> 10;
    const int m   = bm & 1023;
    float h = g_h0[idx];
    int base = c * CL * (Bb * Mm) + bm;
    size_t ybase = (size_t)bb * Tt * Mm + (size_t)(c * CL) * Mm + m;
    #pragma unroll 8
    for (int i = 0; i < CL; i++) {
        const float r  = g_r[base];
        const float xi = g_zi[base] * g_sg[base];
        h = h * r + xi;
        const float ss = h / (1.0f + fabsf(h));
        g_y[ybase] = __uint_as_float(f2tf(ss * g_og[base]));
        base  += Bb * Mm;
        ybase += Mm;
    }
    if (c == NC - 1 && memout) memout[bm] = h;
}

// ---------------------------------------------------------------------------
// Launch
// ---------------------------------------------------------------------------
extern "C" void kernel_launch(void* const* d_in, const int* in_sizes, int n_in,
                              void* d_out, int out_size) {
    (void)in_sizes; (void)n_in;
    const float* x     = (const float*)d_in[0];
    const float* mem   = (const float*)d_in[1];
    const float* wr_w  = (const float*)d_in[2];
    const float* wr_b  = (const float*)d_in[3];
    const float* wi_w  = (const float*)d_in[4];
    const float* wig_w = (const float*)d_in[5];
    const float* wig_b = (const float*)d_in[6];
    const float* wog_w = (const float*)d_in[7];
    const float* wog_b = (const float*)d_in[8];
    const float* wo_w  = (const float*)d_in[9];
    float* outp = (float*)d_out;

    float *p_r, *p_og, *p_zi, *p_sg, *p_y, *p_xc;
    float *p_w0, *p_w1, *p_w2, *p_w3, *p_w4;
    cudaGetSymbolAddress((void**)&p_r,  g_r);
    cudaGetSymbolAddress((void**)&p_og, g_og);
    cudaGetSymbolAddress((void**)&p_zi, g_zi);
    cudaGetSymbolAddress((void**)&p_sg, g_sg);
    cudaGetSymbolAddress((void**)&p_y,  g_y);
    cudaGetSymbolAddress((void**)&p_xc, g_xc);
    cudaGetSymbolAddress((void**)&p_w0, g_w0);
    cudaGetSymbolAddress((void**)&p_w1, g_w1);
    cudaGetSymbolAddress((void**)&p_w2, g_w2);
    cudaGetSymbolAddress((void**)&p_w3, g_w3);
    cudaGetSymbolAddress((void**)&p_w4, g_w4);

    static bool attr_done = false;
    if (!attr_done) {
        cudaFuncSetAttribute(gemm_tf32, cudaFuncAttributeMaxDynamicSharedMemorySize, SMEM_SZ);
        attr_done = true;
    }

    // rna pre-rounding to tf32
    const int nx4 = (PROWS * Mm) / 4;
    const int nw4 = (Mm * Mm) / 4;
    cvt_tf32<<<(nx4 + 255) / 256, 256>>>((const float4*)x, (float4*)p_xc, nx4);
    {
        CvtBatch cb;
        cb.s[0] = (const float4*)wr_w;  cb.d[0] = (float4*)p_w0;
        cb.s[1] = (const float4*)wog_w; cb.d[1] = (float4*)p_w1;
        cb.s[2] = (const float4*)wi_w;  cb.d[2] = (float4*)p_w2;
        cb.s[3] = (const float4*)wig_w; cb.d[3] = (float4*)p_w3;
        cb.s[4] = (const float4*)wo_w;  cb.d[4] = (float4*)p_w4;
        cvt_tf32_w<<<dim3(nw4 / 256, 5), 256>>>(cb);
    }

    // four input projections, batched in one launch (grid.z = 4)
    {
        GemmBatch gb;
        gb.W[0] = p_w0; gb.bias[0] = wr_b;    gb.out[0] = p_r;  gb.act[0] = 1;
        gb.W[1] = p_w1; gb.bias[1] = wog_b;   gb.out[1] = p_og; gb.act[1] = 1;
        gb.W[2] = p_w2; gb.bias[2] = nullptr; gb.out[2] = p_zi; gb.act[2] = 0;
        gb.W[3] = p_w3; gb.bias[3] = wig_b;   gb.out[3] = p_sg; gb.act[3] = 1;
        gb.tmajor = 1;
        dim3 grid(PROWS / 128, Mm / 128, 4);
        gemm_tf32<<<grid, 128, SMEM_SZ>>>(p_xc, gb);
    }

    // chunked scan
    scan_pass1<<<(NC * Bb * Mm) / 256, 256>>>();
    scan_mid<<<(Bb * Mm) / 256, 256>>>(mem);
    float* memout = (out_size >= PROWS * Mm + Bb * Mm) ? (outp + (size_t)PROWS * Mm)
                                                       : nullptr;
    scan_pass2<<<(NC * Bb * Mm) / 256, 256>>>(memout);

    // output projection straight to d_out (p-major)
    {
        GemmBatch gb;
        gb.W[0] = p_w4; gb.bias[0] = nullptr; gb.out[0] = outp; gb.act[0] = 0;
        gb.W[1] = gb.W[2] = gb.W[3] = nullptr;
        gb.bias[1] = gb.bias[2] = gb.bias[3] = nullptr;
        gb.out[1] = gb.out[2] = gb.out[3] = nullptr;
        gb.act[1] = gb.act[2] = gb.act[3] = 0;
        gb.tmajor = 0;
        dim3 grid(PROWS / 128, Mm / 128, 1);
        gemm_tf32<<<grid, 128, SMEM_SZ>>>(p_y, gb);
    }
}